// round 13
// baseline (speedup 1.0000x reference)
#include <cuda_runtime.h>
#include <cstdint>

#define B_    32
#define T_    512
#define D_    512
#define H_    512
#define FOURH 2048
#define NCTA  64           // LSTM CTAs per direction
#define NLSTM 128          // total LSTM CTAs
#define NWORK 168          // GEMM worker CTAs
#define NTILES 4096        // 4 bands x 2 dirs x 32 b x 16 n

typedef unsigned long long ull;

// ---- scratch ----
__device__ float g_xp[2][(size_t)B_ * T_ * FOURH];
__device__ float g_h[2][2][H_ * B_];           // [dir][parity][j*32+b]
__device__ unsigned g_count[2], g_gen[2];      // flat barrier (frozen)
__device__ unsigned g_work;                    // GEMM tile work counter
__device__ unsigned g_band[2][4];              // band completion counters

__device__ __forceinline__ float sigm(float x) { return 1.f / (1.f + __expf(-x)); }
__device__ __forceinline__ float tanh_(float x) { return 2.f / (1.f + __expf(-2.f * x)) - 1.f; }

__device__ __forceinline__ ull fma2(ull a, ull b, ull c) {
    ull d;
    asm("fma.rn.f32x2 %0, %1, %2, %3;" : "=l"(d) : "l"(a), "l"(b), "l"(c));
    return d;
}
union F2U { ull u; float2 f; };
__device__ __forceinline__ float2 u2f(ull v) { F2U x; x.u = v; return x.f; }
__device__ __forceinline__ ull dupf(float v) {
    ull d;
    asm("mov.b64 %0, {%1, %1};" : "=l"(d) : "f"(v));
    return d;
}
__device__ __forceinline__ unsigned ld_acquire(const unsigned* p) {
    unsigned v;
    asm volatile("ld.global.acquire.gpu.u32 %0, [%1];" : "=r"(v) : "l"(p));
    return v;
}

__global__ void reset_counters() {
    if (threadIdx.x == 0) g_work = 0;
    if (threadIdx.x < 8) ((unsigned*)g_band)[threadIdx.x] = 0;
}

// ---------------------------------------------------------------------------
// smem: LSTM role: Wsh [512][32] (64KB) + red [8][32][34] (34KB)
//       GEMM role: As/Bs double-buffered (16KB) + ticket slot (overlaid)
// Total 100,352 B -> 2 CTAs/SM (296 CTAs all wave-1 resident).
// ---------------------------------------------------------------------------
#define W_FLOATS   (512 * 32)
#define RED_STRIDE 34
#define NSPLIT     8
#define RED2(ks, b, c) ((((ks) * 32 + (b)) * RED_STRIDE) + (c))
#define SMEM_BYTES ((W_FLOATS + NSPLIT * 32 * RED_STRIDE) * 4)

// ======================= LSTM role (blockIdx < 128) ========================
__device__ __forceinline__ void lstm_role(
    float* sm, const float* __restrict__ Wfw, const float* __restrict__ Wbw,
    float* __restrict__ out)
{
    float* Wsh = sm;                  // [k][c] natural: k*32 + c
    float* red = sm + W_FLOATS;       // [ks][b][34] + c

    const int tid = threadIdx.x;
    const int dir = blockIdx.x / NCTA;
    const int cta = blockIdx.x % NCTA;
    const int j0  = cta * 8;
    const float* __restrict__ W  = dir ? Wbw : Wfw;
    const float* __restrict__ xp = g_xp[dir];

    // Prologue: Wh slice -> smem natural [k][c], c = gate*8 + jj.
    for (int idx = tid; idx < W_FLOATS; idx += 512) {
        const int k = idx >> 5, c = idx & 31;
        const int gate = c >> 3, jj = c & 7;
        Wsh[k * 32 + c] = W[(size_t)(D_ + k) * FOURH + gate * H_ + j0 + jj];
    }

    // matvec roles (lane=batch remap): tid = ks*64 + ch*32 + b
    const int b_m = tid & 31;                // batch = lane (coalesced h)
    const int ch  = (tid >> 5) & 1;          // col-half: 16 cols
    const int ks  = tid >> 6;                // k-split 0..7 (64 k each)
    // gate roles (first 256 threads)
    const int b_g = tid >> 3, jj_g = tid & 7;
    const bool gate_thread = (tid < 256);

    float cst = 0.f;
    float x0 = 0, x1 = 0, x2 = 0, x3 = 0;   // xp for current step (prefetched)
    __syncthreads();

    for (int s = 0; s < T_; s++) {
        const int t = dir ? (T_ - 1 - s) : s;

        // band boundary: gate, then load xp for this step (not prefetchable)
        if ((s & 127) == 0) {
            if (tid == 0) {
                const unsigned* bp = &g_band[dir][s >> 7];
                while (ld_acquire(bp) < 512u) { }
            }
            __syncthreads();
            if (gate_thread) {
                const size_t xrow = ((size_t)b_g * T_ + t) * FOURH + j0 + jj_g;
                x0 = __ldg(xp + xrow + 0 * H_);
                x1 = __ldg(xp + xrow + 1 * H_);
                x2 = __ldg(xp + xrow + 2 * H_);
                x3 = __ldg(xp + xrow + 3 * H_);
            }
        }

        if (s > 0) {
            // matvec: thread = (ks, ch, b). 16 cols x 1 batch x 64 k.
            // h: scalar ldcg, 128B/warp/k coalesced, no redundancy.
            // W: 4x LDS.128 warp-uniform broadcast. 1 dup-mov per k.
            ull a0 = 0, a1 = 0, a2 = 0, a3 = 0;
            ull a4 = 0, a5 = 0, a6 = 0, a7 = 0;
            const float* hp = g_h[dir][(s - 1) & 1] + ks * 64 * 32 + b_m;
            const float* wp = Wsh + ks * 64 * 32 + ch * 16;
#pragma unroll 4
            for (int k = 0; k < 64; k++) {
                const float hs = __ldcg(hp + k * 32);
                const ull hd = dupf(hs);
                const ulonglong2* w2p = (const ulonglong2*)(wp + k * 32);
                ulonglong2 w01 = w2p[0];
                ulonglong2 w23 = w2p[1];
                ulonglong2 w45 = w2p[2];
                ulonglong2 w67 = w2p[3];
                a0 = fma2(hd, w01.x, a0); a1 = fma2(hd, w01.y, a1);
                a2 = fma2(hd, w23.x, a2); a3 = fma2(hd, w23.y, a3);
                a4 = fma2(hd, w45.x, a4); a5 = fma2(hd, w45.y, a5);
                a6 = fma2(hd, w67.x, a6); a7 = fma2(hd, w67.y, a7);
            }
            const int c0 = ch * 16;
            float* rp = &red[RED2(ks, b_m, c0)];
            *(float2*)(rp + 0)  = u2f(a0);
            *(float2*)(rp + 2)  = u2f(a1);
            *(float2*)(rp + 4)  = u2f(a2);
            *(float2*)(rp + 6)  = u2f(a3);
            *(float2*)(rp + 8)  = u2f(a4);
            *(float2*)(rp + 10) = u2f(a5);
            *(float2*)(rp + 12) = u2f(a6);
            *(float2*)(rp + 14) = u2f(a7);
        }
        __syncthreads();

        float hv_out = 0.f;
        int j = 0;
        if (gate_thread) {
            float z0 = x0, z1 = x1, z2 = x2, z3 = x3;
            if (s > 0) {
#pragma unroll
                for (int kk = 0; kk < NSPLIT; kk++) {
                    z0 += red[RED2(kk, b_g,  0 + jj_g)];
                    z1 += red[RED2(kk, b_g,  8 + jj_g)];
                    z2 += red[RED2(kk, b_g, 16 + jj_g)];
                    z3 += red[RED2(kk, b_g, 24 + jj_g)];
                }
            }
            const float ig = sigm(z0), fg = sigm(z1), og = sigm(z2), gg = tanh_(z3);
            cst = fmaf(fg, cst, ig * gg);
            hv_out = og * tanh_(cst);

            j = j0 + jj_g;
            __stcg(&g_h[dir][s & 1][j * B_ + b_g], hv_out);  // publish ONLY
        }

        __syncthreads();   // g_h publishes done CTA-wide

        // ---- barrier shadow: out[] store + xp(t+1) prefetch overlap the
        //      fence/arrive/spin below --------------------------------------
        if (gate_thread) {
            out[((size_t)b_g * T_ + t) * (2 * H_) + dir * H_ + j] = hv_out;
            const int sn = s + 1;
            if (sn < T_ && (sn & 127) != 0) {
                const int tn = dir ? (T_ - 1 - sn) : sn;
                const size_t xrow = ((size_t)b_g * T_ + tn) * FOURH + j0 + jj_g;
                x0 = __ldg(xp + xrow + 0 * H_);
                x1 = __ldg(xp + xrow + 1 * H_);
                x2 = __ldg(xp + xrow + 2 * H_);
                x3 = __ldg(xp + xrow + 3 * H_);
            }
        }

        if (tid == 0) {
            __threadfence();   // drains g_h publishes (out[] may lag, harmless)
            const unsigned gen = *(volatile unsigned*)&g_gen[dir];
            const unsigned old = atomicAdd(&g_count[dir], 1);
            if (old == NCTA - 1) {
                atomicExch(&g_count[dir], 0);
                __threadfence();
                atomicAdd(&g_gen[dir], 1);
            } else {
                while (ld_acquire(&g_gen[dir]) == gen) { }
            }
        }
        __syncthreads();
    }
}

// ======================= GEMM worker role (blockIdx >= 128) ================
__device__ __forceinline__ void gemm_role(
    float* sm, const float* __restrict__ x,
    const float* __restrict__ Wfw, const float* __restrict__ bfw,
    const float* __restrict__ Wbw, const float* __restrict__ bbw)
{
    float* As = sm;                       // [2][8][128]
    float* Bs = sm + 2048;                // [2][8][128]
    unsigned* ticket = (unsigned*)(sm + 4096);  // CTA-uniform tile id

    const int tid = threadIdx.x;
    const int ar  = tid >> 2;
    const int ac2 = (tid & 3) * 2;
    const int bk  = tid >> 6;
    const int bn2 = (tid & 63) * 2;
    const int tx = tid & 31;
    const int ty = tid >> 5;

    for (;;) {
        if (tid == 0) *ticket = atomicAdd(&g_work, 1u);
        __syncthreads();
        const unsigned id = *ticket;
        if (id >= NTILES) break;

        const int lb   = id >> 10;
        const int rem  = id & 1023;
        const int dir  = rem >> 9;
        const int rem2 = rem & 511;
        const int bi   = rem2 >> 4;
        const int ni   = rem2 & 15;
        const int tband = dir ? (3 - lb) : lb;
        const int m0 = bi * T_ + tband * 128;
        const int n0 = ni * 128;
        const float* __restrict__ Wd = dir ? Wbw : Wfw;
        const float* __restrict__ bd = dir ? bbw : bfw;
        float* __restrict__ C = g_xp[dir];

        const float* Ap = x  + (size_t)(m0 + ar) * D_ + ac2;
        const float* Bp = Wd + (size_t)bk * FOURH + n0 + bn2;

        ull acc[4][4];
#pragma unroll
        for (int p = 0; p < 4; p++)
#pragma unroll
            for (int j = 0; j < 4; j++) acc[p][j] = 0ull;

        float2 av = *(const float2*)(Ap);
        float2 bv = *(const float2*)(Bp);

        for (int k0 = 0; k0 < D_; k0 += 8) {
            const int buf = (k0 >> 3) & 1;
            float* Asb = As + buf * 1024;
            float* Bsb = Bs + buf * 1024;
            Asb[(ac2 + 0) * 128 + ar] = av.x;
            Asb[(ac2 + 1) * 128 + ar] = av.y;
            *(float2*)&Bsb[bk * 128 + bn2] = bv;
            __syncthreads();

            if (k0 + 8 < D_) {
                av = *(const float2*)(Ap + k0 + 8);
                bv = *(const float2*)(Bp + (size_t)(k0 + 8) * FOURH);
            }

#pragma unroll
            for (int kk = 0; kk < 8; kk++) {
                const ulonglong2* ap2 =
                    (const ulonglong2*)&Asb[kk * 128 + ty * 8];
                ulonglong2 A0 = ap2[0], A1 = ap2[1];
                ull am[4] = {A0.x, A0.y, A1.x, A1.y};
                float4 b4 = *(const float4*)&Bsb[kk * 128 + tx * 4];
                ull bdp[4] = {dupf(b4.x), dupf(b4.y), dupf(b4.z), dupf(b4.w)};
#pragma unroll
                for (int p = 0; p < 4; p++)
#pragma unroll
                    for (int j = 0; j < 4; j++)
                        acc[p][j] = fma2(am[p], bdp[j], acc[p][j]);
            }
            __syncthreads();
        }

        float bias[4];
#pragma unroll
        for (int j = 0; j < 4; j++) bias[j] = bd[n0 + tx * 4 + j];

#pragma unroll
        for (int p = 0; p < 4; p++) {
            float2 c0 = u2f(acc[p][0]), c1 = u2f(acc[p][1]);
            float2 c2 = u2f(acc[p][2]), c3 = u2f(acc[p][3]);
            const size_t r0 = (size_t)(m0 + ty * 8 + 2 * p);
            float* cp0 = C + r0 * FOURH + n0 + tx * 4;
            float* cp1 = cp0 + FOURH;
            float4 o0, o1;
            o0.x = c0.x + bias[0]; o0.y = c1.x + bias[1];
            o0.z = c2.x + bias[2]; o0.w = c3.x + bias[3];
            o1.x = c0.y + bias[0]; o1.y = c1.y + bias[1];
            o1.z = c2.y + bias[2]; o1.w = c3.y + bias[3];
            *(float4*)cp0 = o0;
            *(float4*)cp1 = o1;
        }
        __syncthreads();   // fences smem (and ticket) for next iteration

        if (tid == 0) {
            __threadfence();
            atomicAdd(&g_band[dir][lb], 1u);
        }
    }
}

// ======================= unified persistent kernel =========================
__global__ __launch_bounds__(512, 2) void fused_kernel(
    const float* __restrict__ x,
    const float* __restrict__ Wfw, const float* __restrict__ bfw,
    const float* __restrict__ Wbw, const float* __restrict__ bbw,
    float* __restrict__ out)
{
    extern __shared__ float sm[];
    if (blockIdx.x < NLSTM) lstm_role(sm, Wfw, Wbw, out);
    else                    gemm_role(sm, x, Wfw, bfw, Wbw, bbw);
}

// ---------------------------------------------------------------------------
extern "C" void kernel_launch(void* const* d_in, const int* in_sizes, int n_in,
                              void* d_out, int out_size)
{
    const float* x   = (const float*)d_in[0];
    const float* Wfw = (const float*)d_in[1];
    const float* bfw = (const float*)d_in[2];
    const float* Wbw = (const float*)d_in[3];
    const float* bbw = (const float*)d_in[4];
    float* out = (float*)d_out;

    reset_counters<<<1, 32>>>();

    cudaFuncSetAttribute(fused_kernel,
                         cudaFuncAttributeMaxDynamicSharedMemorySize, SMEM_BYTES);
    fused_kernel<<<NLSTM + NWORK, 512, SMEM_BYTES>>>(x, Wfw, bfw, Wbw, bbw, out);
}

// round 14
// speedup vs baseline: 1.1140x; 1.1140x over previous
#include <cuda_runtime.h>
#include <cstdint>

#define B_    32
#define T_    512
#define D_    512
#define H_    512
#define FOURH 2048
#define NCTA  64           // LSTM CTAs per direction
#define NLSTM 128          // total LSTM CTAs
#define NWORK 168          // GEMM worker CTAs
#define NTILES 4096        // 4 bands x 2 dirs x 32 b x 16 n

typedef unsigned long long ull;

// ---- scratch ----
__device__ float g_xp[2][(size_t)B_ * T_ * FOURH];
__device__ float g_h[2][2][H_ * B_];           // [dir][parity][j*32+b]
__device__ unsigned g_count[2], g_gen[2];      // flat barrier (frozen)
__device__ unsigned g_work;                    // GEMM tile work counter
__device__ unsigned g_band[2][4];              // band completion counters

__device__ __forceinline__ float sigm(float x) { return 1.f / (1.f + __expf(-x)); }
__device__ __forceinline__ float tanh_(float x) { return 2.f / (1.f + __expf(-2.f * x)) - 1.f; }

__device__ __forceinline__ ull fma2(ull a, ull b, ull c) {
    ull d;
    asm("fma.rn.f32x2 %0, %1, %2, %3;" : "=l"(d) : "l"(a), "l"(b), "l"(c));
    return d;
}
union F2U { ull u; float2 f; };
__device__ __forceinline__ float2 u2f(ull v) { F2U x; x.u = v; return x.f; }
__device__ __forceinline__ ull dupf(float v) {
    ull d;
    asm("mov.b64 %0, {%1, %1};" : "=l"(d) : "f"(v));
    return d;
}
__device__ __forceinline__ unsigned ld_acquire(const unsigned* p) {
    unsigned v;
    asm volatile("ld.global.acquire.gpu.u32 %0, [%1];" : "=r"(v) : "l"(p));
    return v;
}
// release-fused atomics: ordering folded into the atomic, no MEMBAR.GPU
__device__ __forceinline__ unsigned atom_add_release(unsigned* p, unsigned v) {
    unsigned old;
    asm volatile("atom.add.release.gpu.u32 %0, [%1], %2;"
                 : "=r"(old) : "l"(p), "r"(v) : "memory");
    return old;
}
__device__ __forceinline__ void red_add_release(unsigned* p, unsigned v) {
    asm volatile("red.add.release.gpu.u32 [%0], %1;"
                 :: "l"(p), "r"(v) : "memory");
}
union LD4 { float4 f; ulonglong2 u; };

__global__ void reset_counters() {
    if (threadIdx.x == 0) g_work = 0;
    if (threadIdx.x < 8) ((unsigned*)g_band)[threadIdx.x] = 0;
}

// ---------------------------------------------------------------------------
// smem: LSTM role: Wsh [512][32] (64KB) + red [8][32][34] (34KB)
//       GEMM role: As/Bs double-buffered (16KB) + ticket slot (overlaid)
// Total 100,352 B -> 2 CTAs/SM (296 CTAs all wave-1 resident).
// ---------------------------------------------------------------------------
#define W_FLOATS   (512 * 32)
#define RED_STRIDE 34
#define NSPLIT     8
#define RED2(ks, b, c) ((((ks) * 32 + (b)) * RED_STRIDE) + (c))
#define SMEM_BYTES ((W_FLOATS + NSPLIT * 32 * RED_STRIDE) * 4)

// ======================= LSTM role (blockIdx < 128) ========================
__device__ __forceinline__ void lstm_role(
    float* sm, const float* __restrict__ Wfw, const float* __restrict__ Wbw,
    float* __restrict__ out)
{
    float* Wsh = sm;                  // [k][c] natural: k*32 + c
    float* red = sm + W_FLOATS;       // [ks][b][34] + c

    const int tid = threadIdx.x;
    const int dir = blockIdx.x / NCTA;
    const int cta = blockIdx.x % NCTA;
    const int j0  = cta * 8;
    const float* __restrict__ W  = dir ? Wbw : Wfw;
    const float* __restrict__ xp = g_xp[dir];

    // Prologue: Wh slice -> smem natural [k][c], c = gate*8 + jj.
    for (int idx = tid; idx < W_FLOATS; idx += 512) {
        const int k = idx >> 5, c = idx & 31;
        const int gate = c >> 3, jj = c & 7;
        Wsh[k * 32 + c] = W[(size_t)(D_ + k) * FOURH + gate * H_ + j0 + jj];
    }

    // matvec roles (R11 tiling — best measured): tid = ks*64 + cg*8 + bq
    const int bq = tid & 7;
    const int cg = (tid >> 3) & 7;
    const int ks = tid >> 6;
    // gate roles (first 256 threads)
    const int b_g = tid >> 3, jj_g = tid & 7;
    const bool gate_thread = (tid < 256);

    float cst = 0.f;
    float x0 = 0, x1 = 0, x2 = 0, x3 = 0;   // xp for current step (prefetched)
    __syncthreads();

    for (int s = 0; s < T_; s++) {
        const int t = dir ? (T_ - 1 - s) : s;

        // band boundary: gate, then load xp for this step (not prefetchable)
        if ((s & 127) == 0) {
            if (tid == 0) {
                const unsigned* bp = &g_band[dir][s >> 7];
                while (ld_acquire(bp) < 512u) { }
            }
            __syncthreads();
            if (gate_thread) {
                const size_t xrow = ((size_t)b_g * T_ + t) * FOURH + j0 + jj_g;
                x0 = __ldg(xp + xrow + 0 * H_);
                x1 = __ldg(xp + xrow + 1 * H_);
                x2 = __ldg(xp + xrow + 2 * H_);
                x3 = __ldg(xp + xrow + 3 * H_);
            }
        }

        if (s > 0) {
            ull a0x = 0, a0y = 0, a1x = 0, a1y = 0;
            ull a2x = 0, a2y = 0, a3x = 0, a3y = 0;
            const float* hbase = g_h[dir][(s - 1) & 1] + ks * 64 * 32 + 4 * bq;
            const float* wbase = Wsh + ks * 64 * 32 + 4 * cg;
#pragma unroll 8
            for (int k = 0; k < 64; k++) {
                LD4 hv; hv.f = __ldcg((const float4*)(hbase + k * 32));
                ulonglong2 wv = *(const ulonglong2*)(wbase + k * 32);
                const ull h0 = dupf(hv.f.x), h1 = dupf(hv.f.y);
                const ull h2 = dupf(hv.f.z), h3 = dupf(hv.f.w);
                a0x = fma2(h0, wv.x, a0x); a0y = fma2(h0, wv.y, a0y);
                a1x = fma2(h1, wv.x, a1x); a1y = fma2(h1, wv.y, a1y);
                a2x = fma2(h2, wv.x, a2x); a2y = fma2(h2, wv.y, a2y);
                a3x = fma2(h3, wv.x, a3x); a3y = fma2(h3, wv.y, a3y);
            }
            const int c0 = 4 * cg;
            const int bb = 4 * bq;
            *(float2*)&red[RED2(ks, bb + 0, c0)]     = u2f(a0x);
            *(float2*)&red[RED2(ks, bb + 0, c0 + 2)] = u2f(a0y);
            *(float2*)&red[RED2(ks, bb + 1, c0)]     = u2f(a1x);
            *(float2*)&red[RED2(ks, bb + 1, c0 + 2)] = u2f(a1y);
            *(float2*)&red[RED2(ks, bb + 2, c0)]     = u2f(a2x);
            *(float2*)&red[RED2(ks, bb + 2, c0 + 2)] = u2f(a2y);
            *(float2*)&red[RED2(ks, bb + 3, c0)]     = u2f(a3x);
            *(float2*)&red[RED2(ks, bb + 3, c0 + 2)] = u2f(a3y);
        }
        __syncthreads();

        float hv_out = 0.f;
        int j = 0;
        if (gate_thread) {
            float z0 = x0, z1 = x1, z2 = x2, z3 = x3;
            if (s > 0) {
#pragma unroll
                for (int kk = 0; kk < NSPLIT; kk++) {
                    z0 += red[RED2(kk, b_g,  0 + jj_g)];
                    z1 += red[RED2(kk, b_g,  8 + jj_g)];
                    z2 += red[RED2(kk, b_g, 16 + jj_g)];
                    z3 += red[RED2(kk, b_g, 24 + jj_g)];
                }
            }
            const float ig = sigm(z0), fg = sigm(z1), og = sigm(z2), gg = tanh_(z3);
            cst = fmaf(fg, cst, ig * gg);
            hv_out = og * tanh_(cst);

            j = j0 + jj_g;
            __stcg(&g_h[dir][s & 1][j * B_ + b_g], hv_out);  // publish ONLY
        }

        __syncthreads();   // g_h publishes done CTA-wide

        // ---- barrier shadow: out[] store + xp(t+1) prefetch overlap the
        //      arrive/spin below -------------------------------------------
        if (gate_thread) {
            out[((size_t)b_g * T_ + t) * (2 * H_) + dir * H_ + j] = hv_out;
            const int sn = s + 1;
            if (sn < T_ && (sn & 127) != 0) {
                const int tn = dir ? (T_ - 1 - sn) : sn;
                const size_t xrow = ((size_t)b_g * T_ + tn) * FOURH + j0 + jj_g;
                x0 = __ldg(xp + xrow + 0 * H_);
                x1 = __ldg(xp + xrow + 1 * H_);
                x2 = __ldg(xp + xrow + 2 * H_);
                x3 = __ldg(xp + xrow + 3 * H_);
            }
        }

        if (tid == 0) {
            // release-fused arrival: cumulativity (syncthreads above) makes
            // all threads' g_h publishes part of the release set. No MEMBAR.
            const unsigned gen = *(volatile unsigned*)&g_gen[dir];
            const unsigned old = atom_add_release(&g_count[dir], 1u);
            if (old == NCTA - 1) {
                atomicExch(&g_count[dir], 0);
                red_add_release(&g_gen[dir], 1u);   // release covers the exch
            } else {
                while (ld_acquire(&g_gen[dir]) == gen) { }
            }
        }
        __syncthreads();
    }
}

// ======================= GEMM worker role (blockIdx >= 128) ================
__device__ __forceinline__ void gemm_role(
    float* sm, const float* __restrict__ x,
    const float* __restrict__ Wfw, const float* __restrict__ bfw,
    const float* __restrict__ Wbw, const float* __restrict__ bbw)
{
    float* As = sm;                       // [2][8][128]
    float* Bs = sm + 2048;                // [2][8][128]
    unsigned* ticket = (unsigned*)(sm + 4096);  // CTA-uniform tile id

    const int tid = threadIdx.x;
    const int ar  = tid >> 2;
    const int ac2 = (tid & 3) * 2;
    const int bk  = tid >> 6;
    const int bn2 = (tid & 63) * 2;
    const int tx = tid & 31;
    const int ty = tid >> 5;

    for (;;) {
        if (tid == 0) *ticket = atomicAdd(&g_work, 1u);
        __syncthreads();
        const unsigned id = *ticket;
        if (id >= NTILES) break;

        const int lb   = id >> 10;
        const int rem  = id & 1023;
        const int dir  = rem >> 9;
        const int rem2 = rem & 511;
        const int bi   = rem2 >> 4;
        const int ni   = rem2 & 15;
        const int tband = dir ? (3 - lb) : lb;
        const int m0 = bi * T_ + tband * 128;
        const int n0 = ni * 128;
        const float* __restrict__ Wd = dir ? Wbw : Wfw;
        const float* __restrict__ bd = dir ? bbw : bfw;
        float* __restrict__ C = g_xp[dir];

        const float* Ap = x  + (size_t)(m0 + ar) * D_ + ac2;
        const float* Bp = Wd + (size_t)bk * FOURH + n0 + bn2;

        ull acc[4][4];
#pragma unroll
        for (int p = 0; p < 4; p++)
#pragma unroll
            for (int j = 0; j < 4; j++) acc[p][j] = 0ull;

        float2 av = *(const float2*)(Ap);
        float2 bv = *(const float2*)(Bp);

        for (int k0 = 0; k0 < D_; k0 += 8) {
            const int buf = (k0 >> 3) & 1;
            float* Asb = As + buf * 1024;
            float* Bsb = Bs + buf * 1024;
            Asb[(ac2 + 0) * 128 + ar] = av.x;
            Asb[(ac2 + 1) * 128 + ar] = av.y;
            *(float2*)&Bsb[bk * 128 + bn2] = bv;
            __syncthreads();

            if (k0 + 8 < D_) {
                av = *(const float2*)(Ap + k0 + 8);
                bv = *(const float2*)(Bp + (size_t)(k0 + 8) * FOURH);
            }

#pragma unroll
            for (int kk = 0; kk < 8; kk++) {
                const ulonglong2* ap2 =
                    (const ulonglong2*)&Asb[kk * 128 + ty * 8];
                ulonglong2 A0 = ap2[0], A1 = ap2[1];
                ull am[4] = {A0.x, A0.y, A1.x, A1.y};
                float4 b4 = *(const float4*)&Bsb[kk * 128 + tx * 4];
                ull bdp[4] = {dupf(b4.x), dupf(b4.y), dupf(b4.z), dupf(b4.w)};
#pragma unroll
                for (int p = 0; p < 4; p++)
#pragma unroll
                    for (int j = 0; j < 4; j++)
                        acc[p][j] = fma2(am[p], bdp[j], acc[p][j]);
            }
            __syncthreads();
        }

        float bias[4];
#pragma unroll
        for (int j = 0; j < 4; j++) bias[j] = bd[n0 + tx * 4 + j];

#pragma unroll
        for (int p = 0; p < 4; p++) {
            float2 c0 = u2f(acc[p][0]), c1 = u2f(acc[p][1]);
            float2 c2 = u2f(acc[p][2]), c3 = u2f(acc[p][3]);
            const size_t r0 = (size_t)(m0 + ty * 8 + 2 * p);
            float* cp0 = C + r0 * FOURH + n0 + tx * 4;
            float* cp1 = cp0 + FOURH;
            float4 o0, o1;
            o0.x = c0.x + bias[0]; o0.y = c1.x + bias[1];
            o0.z = c2.x + bias[2]; o0.w = c3.x + bias[3];
            o1.x = c0.y + bias[0]; o1.y = c1.y + bias[1];
            o1.z = c2.y + bias[2]; o1.w = c3.y + bias[3];
            *(float4*)cp0 = o0;
            *(float4*)cp1 = o1;
        }
        __syncthreads();   // fences smem (and ticket) for next iteration

        if (tid == 0) {
            red_add_release(&g_band[dir][lb], 1u);  // release-fused publish
        }
    }
}

// ======================= unified persistent kernel =========================
__global__ __launch_bounds__(512, 2) void fused_kernel(
    const float* __restrict__ x,
    const float* __restrict__ Wfw, const float* __restrict__ bfw,
    const float* __restrict__ Wbw, const float* __restrict__ bbw,
    float* __restrict__ out)
{
    extern __shared__ float sm[];
    if (blockIdx.x < NLSTM) lstm_role(sm, Wfw, Wbw, out);
    else                    gemm_role(sm, x, Wfw, bfw, Wbw, bbw);
}

// ---------------------------------------------------------------------------
extern "C" void kernel_launch(void* const* d_in, const int* in_sizes, int n_in,
                              void* d_out, int out_size)
{
    const float* x   = (const float*)d_in[0];
    const float* Wfw = (const float*)d_in[1];
    const float* bfw = (const float*)d_in[2];
    const float* Wbw = (const float*)d_in[3];
    const float* bbw = (const float*)d_in[4];
    float* out = (float*)d_out;

    reset_counters<<<1, 32>>>();

    cudaFuncSetAttribute(fused_kernel,
                         cudaFuncAttributeMaxDynamicSharedMemorySize, SMEM_BYTES);
    fused_kernel<<<NLSTM + NWORK, 512, SMEM_BYTES>>>(x, Wfw, bfw, Wbw, bbw, out);
}